// round 12
// baseline (speedup 1.0000x reference)
#include <cuda_runtime.h>
#include <cuda_fp16.h>

#define NN 500000
#define NE 8000000
#define NG 1024

// Scratch (static __device__ — no allocations allowed)
__device__ float  g_deg[NN];          // zeroed by memset; self-loop +1 in prep1
__device__ float  g_dinv[NN];
__device__ float2 g_q1[NN];
__device__ float2 g_S1[NN];
__device__ __align__(32) uint4 g_q2h[NN * 2]; // 16 fp16/node = dinv*relu(y@W1+b1)
__device__ __align__(32) uint4 g_S2h[NN * 2]; // fp16 accumulator
__device__ float  g_psum[NG];
__device__ float  g_pcnt[NG];

// Block-local dtype probe: node ids are in [0, NN), so int32 data reinterpreted
// as int64 yields out-of-range values with probability ~1. First 256 words are
// 2 KB (in-bounds for either dtype) and L2-hot after the first block. No global
// state, no cross-kernel ordering, no replay reset needed.
__device__ __forceinline__ int probe_is64(const void* ei) {
    int bad = 0;
    if (threadIdx.x < 256) {
        long long v = ((const long long*)ei)[threadIdx.x];
        bad = (v < 0 || v >= NN);
    }
    return !__syncthreads_or(bad);
}

// 4 edges per thread, dst stream only: batch loads, then batch reds (MLP).
__global__ void __launch_bounds__(512) k_degree(const void* __restrict__ ei) {
    const int is64 = probe_is64(ei);
    long long e = ((long long)blockIdx.x * blockDim.x + threadIdx.x) * 4;
    if (e >= NE) return;
    int t0, t1, t2, t3;
    if (is64) {
        longlong2 a = __ldcg((const longlong2*)((const long long*)ei + NE + e));
        longlong2 b = __ldcg((const longlong2*)((const long long*)ei + NE + e + 2));
        t0 = (int)a.x; t1 = (int)a.y; t2 = (int)b.x; t3 = (int)b.y;
    } else {
        int4 a = __ldcg((const int4*)((const int*)ei + NE + e));
        t0 = a.x; t1 = a.y; t2 = a.z; t3 = a.w;
    }
    atomicAdd(&g_deg[t0], 1.0f);
    atomicAdd(&g_deg[t1], 1.0f);
    atomicAdd(&g_deg[t2], 1.0f);
    atomicAdd(&g_deg[t3], 1.0f);
}

__global__ void k_prep1(const float* __restrict__ x) {
    int i = blockIdx.x * blockDim.x + threadIdx.x;
    if (i >= NN) return;
    float d = rsqrtf(g_deg[i] + 1.0f);    // +1 = self loop (deg memset to 0)
    g_dinv[i] = d;
    float2 xv = ((const float2*)x)[i];
    float2 q = make_float2(d * xv.x, d * xv.y);
    g_q1[i] = q;
    g_S1[i] = q;                          // self-loop contribution
}

// 4 edges per thread: all index loads, then all gathers, then all reds.
__global__ void __launch_bounds__(512) k_edge1(const void* __restrict__ ei) {
    const int is64 = probe_is64(ei);
    long long e = ((long long)blockIdx.x * blockDim.x + threadIdx.x) * 4;
    if (e >= NE) return;
    int s0, s1, s2, s3, t0, t1, t2, t3;
    if (is64) {
        longlong2 sa = __ldcg((const longlong2*)((const long long*)ei + e));
        longlong2 sb = __ldcg((const longlong2*)((const long long*)ei + e + 2));
        longlong2 ta = __ldcg((const longlong2*)((const long long*)ei + NE + e));
        longlong2 tb = __ldcg((const longlong2*)((const long long*)ei + NE + e + 2));
        s0 = (int)sa.x; s1 = (int)sa.y; s2 = (int)sb.x; s3 = (int)sb.y;
        t0 = (int)ta.x; t1 = (int)ta.y; t2 = (int)tb.x; t3 = (int)tb.y;
    } else {
        int4 sa = __ldcg((const int4*)((const int*)ei + e));
        int4 ta = __ldcg((const int4*)((const int*)ei + NE + e));
        s0 = sa.x; s1 = sa.y; s2 = sa.z; s3 = sa.w;
        t0 = ta.x; t1 = ta.y; t2 = ta.z; t3 = ta.w;
    }
    float2 v0 = __ldcg(&g_q1[s0]);
    float2 v1 = __ldcg(&g_q1[s1]);
    float2 v2 = __ldcg(&g_q1[s2]);
    float2 v3 = __ldcg(&g_q1[s3]);
    atomicAdd(&g_S1[t0], v0);             // red.global.v2.f32
    atomicAdd(&g_S1[t1], v1);
    atomicAdd(&g_S1[t2], v2);
    atomicAdd(&g_S1[t3], v3);
}

// 256-bit store (sm_100+)
__device__ __forceinline__ void st256(void* p, uint4 a, uint4 b) {
    asm volatile("st.global.cg.v8.b32 [%0], {%1,%2,%3,%4,%5,%6,%7,%8};"
                 :: "l"(p), "r"(a.x), "r"(a.y), "r"(a.z), "r"(a.w),
                    "r"(b.x), "r"(b.y), "r"(b.z), "r"(b.w) : "memory");
}

__global__ void k_mid(const float* __restrict__ W1, const float* __restrict__ b1) {
    int i = blockIdx.x * blockDim.x + threadIdx.x;
    if (i >= NN) return;
    float d = g_dinv[i];
    float2 Sv = g_S1[i];
    float yx = d * Sv.x;
    float yy = d * Sv.y;
    __half2 h2[8];
#pragma unroll
    for (int c = 0; c < 4; c++) {
        float4 w0 = ((const float4*)W1)[c];          // W1 row 0
        float4 w1 = ((const float4*)(W1 + 16))[c];   // W1 row 1
        float4 bb = ((const float4*)b1)[c];
        float hx = d * fmaxf(fmaf(yx, w0.x, fmaf(yy, w1.x, bb.x)), 0.0f);
        float hy = d * fmaxf(fmaf(yx, w0.y, fmaf(yy, w1.y, bb.y)), 0.0f);
        float hz = d * fmaxf(fmaf(yx, w0.z, fmaf(yy, w1.z, bb.z)), 0.0f);
        float hw = d * fmaxf(fmaf(yx, w0.w, fmaf(yy, w1.w, bb.w)), 0.0f);
        h2[2 * c + 0] = __floats2half2_rn(hx, hy);
        h2[2 * c + 1] = __floats2half2_rn(hz, hw);
    }
    uint4* pq = (uint4*)h2;
    st256(&g_q2h[i * 2], pq[0], pq[1]);
    st256(&g_S2h[i * 2], pq[0], pq[1]);   // self loop
}

// 2 edges per thread: 2 index loads, 2x256-bit gathers, then 4x128-bit reds.
__global__ void __launch_bounds__(512) k_edge2(const void* __restrict__ ei) {
    const int is64 = probe_is64(ei);
    long long e = ((long long)blockIdx.x * blockDim.x + threadIdx.x) * 2;
    if (e >= NE) return;
    int s0, s1, t0, t1;
    if (is64) {
        longlong2 sv = __ldcg((const longlong2*)((const long long*)ei + e));
        longlong2 tv = __ldcg((const longlong2*)((const long long*)ei + NE + e));
        s0 = (int)sv.x; s1 = (int)sv.y; t0 = (int)tv.x; t1 = (int)tv.y;
    } else {
        int2 sv = __ldcg((const int2*)((const int*)ei + e));
        int2 tv = __ldcg((const int2*)((const int*)ei + NE + e));
        s0 = sv.x; s1 = sv.y; t0 = tv.x; t1 = tv.y;
    }
    unsigned a0, a1, a2, a3, a4, a5, a6, a7;
    unsigned b0, b1, b2, b3, b4, b5, b6, b7;
    asm volatile("ld.global.cg.v8.b32 {%0,%1,%2,%3,%4,%5,%6,%7}, [%8];"
                 : "=r"(a0), "=r"(a1), "=r"(a2), "=r"(a3),
                   "=r"(a4), "=r"(a5), "=r"(a6), "=r"(a7)
                 : "l"(&g_q2h[(long long)s0 * 2]));
    asm volatile("ld.global.cg.v8.b32 {%0,%1,%2,%3,%4,%5,%6,%7}, [%8];"
                 : "=r"(b0), "=r"(b1), "=r"(b2), "=r"(b3),
                   "=r"(b4), "=r"(b5), "=r"(b6), "=r"(b7)
                 : "l"(&g_q2h[(long long)s1 * 2]));
    uint4* d0 = &g_S2h[(long long)t0 * 2];
    uint4* d1 = &g_S2h[(long long)t1 * 2];
    asm volatile("red.global.add.noftz.v4.f16x2 [%0], {%1,%2,%3,%4};"
                 :: "l"(d0), "r"(a0), "r"(a1), "r"(a2), "r"(a3) : "memory");
    asm volatile("red.global.add.noftz.v4.f16x2 [%0], {%1,%2,%3,%4};"
                 :: "l"(d0 + 1), "r"(a4), "r"(a5), "r"(a6), "r"(a7) : "memory");
    asm volatile("red.global.add.noftz.v4.f16x2 [%0], {%1,%2,%3,%4};"
                 :: "l"(d1), "r"(b0), "r"(b1), "r"(b2), "r"(b3) : "memory");
    asm volatile("red.global.add.noftz.v4.f16x2 [%0], {%1,%2,%3,%4};"
                 :: "l"(d1 + 1), "r"(b4), "r"(b5), "r"(b6), "r"(b7) : "memory");
}

// Packed fp32x2 FMA (Blackwell sm_100a+): d = a*b + c on two f32 lanes.
__device__ __forceinline__ unsigned long long fma_f32x2(
    unsigned long long a, unsigned long long b, unsigned long long c) {
    unsigned long long d;
    asm("fma.rn.f32x2 %0, %1, %2, %3;" : "=l"(d) : "l"(a), "l"(b), "l"(c));
    return d;
}
__device__ __forceinline__ unsigned long long pack2(float lo, float hi) {
    unsigned long long r;
    asm("mov.b64 %0, {%1, %2};" : "=l"(r) : "f"(lo), "f"(hi));
    return r;
}
__device__ __forceinline__ float2 unpack2(unsigned long long v) {
    float lo, hi;
    asm("mov.b64 {%0, %1}, %2;" : "=f"(lo), "=f"(hi) : "l"(v));
    return make_float2(lo, hi);
}

__global__ void k_pool(const void* __restrict__ ei,
                       const void* __restrict__ batch,
                       const float* __restrict__ W2, const float* __restrict__ b2,
                       const float* __restrict__ Wl) {
    const int is64 = probe_is64(ei);      // batch shares the index dtype regime
    // W2 as pairs along the 32-output axis: sW2p[j][kp] = (W2[j][2kp], W2[j][2kp+1])
    __shared__ unsigned long long sW2p[16 * 16];
    __shared__ unsigned long long sb2p[16];
    __shared__ unsigned long long sWlp[16];
    for (int j = threadIdx.x; j < 256; j += blockDim.x)
        sW2p[j] = ((const unsigned long long*)W2)[j];
    if (threadIdx.x < 16) {
        sb2p[threadIdx.x] = ((const unsigned long long*)b2)[threadIdx.x];
        sWlp[threadIdx.x] = ((const unsigned long long*)Wl)[threadIdx.x];
    }
    __syncthreads();

    int i = blockIdx.x * blockDim.x + threadIdx.x;
    float val = 0.0f;
    int g = -1;
    if (i < NN) {
        float d = g_dinv[i];
        uint4 a = __ldcg(&g_S2h[i * 2 + 0]);
        uint4 b = __ldcg(&g_S2h[i * 2 + 1]);
        unsigned long long zz[16];        // (z[j], z[j]) broadcast pairs
        const __half2* ah = (const __half2*)&a;
        const __half2* bh = (const __half2*)&b;
#pragma unroll
        for (int j = 0; j < 4; j++) {
            float2 f = __half22float2(ah[j]);
            zz[2 * j + 0] = pack2(d * f.x, d * f.x);
            zz[2 * j + 1] = pack2(d * f.y, d * f.y);
            float2 f2 = __half22float2(bh[j]);
            zz[8 + 2 * j + 0] = pack2(d * f2.x, d * f2.x);
            zz[8 + 2 * j + 1] = pack2(d * f2.y, d * f2.y);
        }
        float s = 0.0f;
#pragma unroll
        for (int kp = 0; kp < 16; kp++) {
            unsigned long long acc = sb2p[kp];
#pragma unroll
            for (int j = 0; j < 16; j++)
                acc = fma_f32x2(zz[j], sW2p[j * 16 + kp], acc);
            float2 u = unpack2(acc);
            float2 wl = unpack2(sWlp[kp]);
            s = fmaf(fmaxf(u.x, 0.0f), wl.x, s);
            s = fmaf(fmaxf(u.y, 0.0f), wl.y, s);
        }
        val = s;
        g = is64 ? (int)__ldcg((const long long*)batch + i)
                 : __ldcg((const int*)batch + i);
    }

    // batch is sorted -> contiguous equal-g runs. Segmented warp reduction to
    // avoid ~500k same-address global atomics.
    float cnt = (g >= 0) ? 1.0f : 0.0f;
    const unsigned full = 0xffffffffu;
    int lane = threadIdx.x & 31;
#pragma unroll
    for (int off = 1; off < 32; off <<= 1) {
        float vo = __shfl_down_sync(full, val, off);
        float co = __shfl_down_sync(full, cnt, off);
        int   go = __shfl_down_sync(full, g,   off);
        if (lane + off < 32 && go == g) { val += vo; cnt += co; }
    }
    int gup = __shfl_up_sync(full, g, 1);
    if (g >= 0 && (lane == 0 || gup != g)) {
        atomicAdd(&g_psum[g], val);
        atomicAdd(&g_pcnt[g], cnt);
    }
}

__global__ void k_out(float* __restrict__ out, const float* __restrict__ bl) {
    int g = blockIdx.x * blockDim.x + threadIdx.x;
    if (g < NG) out[g] = g_psum[g] / fmaxf(g_pcnt[g], 1.0f) + bl[0];
}

extern "C" void kernel_launch(void* const* d_in, const int* in_sizes, int n_in,
                              void* d_out, int out_size) {
    const float* x     = (const float*)d_in[0];
    const void*  ei    = d_in[1];
    const void*  batch = d_in[2];
    const float* W1    = (const float*)d_in[3];
    const float* b1    = (const float*)d_in[4];
    const float* W2    = (const float*)d_in[5];
    const float* b2    = (const float*)d_in[6];
    const float* Wl    = (const float*)d_in[7];
    const float* bl    = (const float*)d_in[8];
    float* out = (float*)d_out;

    // Zero-init via memset nodes (graph-capturable; no allocation).
    void *p_deg = nullptr, *p_psum = nullptr, *p_pcnt = nullptr;
    cudaGetSymbolAddress(&p_deg, g_deg);
    cudaGetSymbolAddress(&p_psum, g_psum);
    cudaGetSymbolAddress(&p_pcnt, g_pcnt);
    cudaMemsetAsync(p_deg, 0, NN * sizeof(float));
    cudaMemsetAsync(p_psum, 0, NG * sizeof(float));
    cudaMemsetAsync(p_pcnt, 0, NG * sizeof(float));

    const int TB = 256;
    const int EB = 512;                   // edge kernels: bigger blocks
    k_degree<<<(NE / 4 + EB - 1) / EB, EB>>>(ei);
    k_prep1 <<<(NN + TB - 1) / TB, TB>>>(x);
    k_edge1 <<<(NE / 4 + EB - 1) / EB, EB>>>(ei);
    k_mid   <<<(NN + TB - 1) / TB, TB>>>(W1, b1);
    k_edge2 <<<(NE / 2 + EB - 1) / EB, EB>>>(ei);
    k_pool  <<<(NN + TB - 1) / TB, TB>>>(ei, batch, W2, b2, Wl);
    k_out   <<<(NG + TB - 1) / TB, TB>>>(out, bl);
}

// round 13
// speedup vs baseline: 1.0241x; 1.0241x over previous
#include <cuda_runtime.h>
#include <cuda_fp16.h>

#define NN 500000
#define NE 8000000
#define NG 1024

// Scratch (static __device__ — no allocations allowed)
__device__ int    g_is64;
__device__ float  g_deg[NN];
__device__ float  g_dinv[NN];
__device__ float2 g_q1[NN];
__device__ float2 g_S1[NN];
__device__ __align__(32) uint4 g_q2h[NN * 2]; // 16 fp16/node = dinv*relu(y@W1+b1)
__device__ __align__(32) uint4 g_S2h[NN * 2]; // fp16 accumulator
__device__ float  g_psum[NG];
__device__ float  g_pcnt[NG];

// init + dtype detect fused. Probe first 256 words as int64: node ids are in
// [0, NN), so int32 data reinterpreted as int64 is out of range w.p. ~1.
__global__ void k_init(const void* ei) {
    int i = blockIdx.x * blockDim.x + threadIdx.x;
    if (i == 0) g_is64 = 1;
    if (i < NN) g_deg[i] = 1.0f;          // self loop
    if (i < NG) { g_psum[i] = 0.0f; g_pcnt[i] = 0.0f; }
    if (blockIdx.x == 1) {                // one block probes; consumed by later
        long long v = ((const long long*)ei)[threadIdx.x]; // launches only
        if (v < 0 || v >= NN) atomicAnd(&g_is64, 0);
    }
}

// 4 edges per thread, dst stream only: batch loads, then batch reds (MLP).
__global__ void __launch_bounds__(512) k_degree(const void* __restrict__ ei) {
    long long e = ((long long)blockIdx.x * blockDim.x + threadIdx.x) * 4;
    if (e >= NE) return;
    int t0, t1, t2, t3;
    if (g_is64) {
        longlong2 a = __ldcg((const longlong2*)((const long long*)ei + NE + e));
        longlong2 b = __ldcg((const longlong2*)((const long long*)ei + NE + e + 2));
        t0 = (int)a.x; t1 = (int)a.y; t2 = (int)b.x; t3 = (int)b.y;
    } else {
        int4 a = __ldcg((const int4*)((const int*)ei + NE + e));
        t0 = a.x; t1 = a.y; t2 = a.z; t3 = a.w;
    }
    atomicAdd(&g_deg[t0], 1.0f);
    atomicAdd(&g_deg[t1], 1.0f);
    atomicAdd(&g_deg[t2], 1.0f);
    atomicAdd(&g_deg[t3], 1.0f);
}

__global__ void k_prep1(const float* __restrict__ x) {
    int i = blockIdx.x * blockDim.x + threadIdx.x;
    if (i >= NN) return;
    float d = rsqrtf(g_deg[i]);           // deg >= 1 always (self loop)
    g_dinv[i] = d;
    float2 xv = ((const float2*)x)[i];
    float2 q = make_float2(d * xv.x, d * xv.y);
    g_q1[i] = q;
    g_S1[i] = q;                          // self-loop contribution
}

// 4 edges per thread: all index loads, then all gathers, then all reds.
__global__ void __launch_bounds__(512) k_edge1(const void* __restrict__ ei) {
    long long e = ((long long)blockIdx.x * blockDim.x + threadIdx.x) * 4;
    if (e >= NE) return;
    int s0, s1, s2, s3, t0, t1, t2, t3;
    if (g_is64) {
        longlong2 sa = __ldcg((const longlong2*)((const long long*)ei + e));
        longlong2 sb = __ldcg((const longlong2*)((const long long*)ei + e + 2));
        longlong2 ta = __ldcg((const longlong2*)((const long long*)ei + NE + e));
        longlong2 tb = __ldcg((const longlong2*)((const long long*)ei + NE + e + 2));
        s0 = (int)sa.x; s1 = (int)sa.y; s2 = (int)sb.x; s3 = (int)sb.y;
        t0 = (int)ta.x; t1 = (int)ta.y; t2 = (int)tb.x; t3 = (int)tb.y;
    } else {
        int4 sa = __ldcg((const int4*)((const int*)ei + e));
        int4 ta = __ldcg((const int4*)((const int*)ei + NE + e));
        s0 = sa.x; s1 = sa.y; s2 = sa.z; s3 = sa.w;
        t0 = ta.x; t1 = ta.y; t2 = ta.z; t3 = ta.w;
    }
    float2 v0 = __ldcg(&g_q1[s0]);
    float2 v1 = __ldcg(&g_q1[s1]);
    float2 v2 = __ldcg(&g_q1[s2]);
    float2 v3 = __ldcg(&g_q1[s3]);
    atomicAdd(&g_S1[t0], v0);             // red.global.v2.f32
    atomicAdd(&g_S1[t1], v1);
    atomicAdd(&g_S1[t2], v2);
    atomicAdd(&g_S1[t3], v3);
}

// 256-bit store (sm_100+)
__device__ __forceinline__ void st256(void* p, uint4 a, uint4 b) {
    asm volatile("st.global.cg.v8.b32 [%0], {%1,%2,%3,%4,%5,%6,%7,%8};"
                 :: "l"(p), "r"(a.x), "r"(a.y), "r"(a.z), "r"(a.w),
                    "r"(b.x), "r"(b.y), "r"(b.z), "r"(b.w) : "memory");
}

__global__ void k_mid(const float* __restrict__ W1, const float* __restrict__ b1) {
    int i = blockIdx.x * blockDim.x + threadIdx.x;
    if (i >= NN) return;
    float d = g_dinv[i];
    float2 Sv = g_S1[i];
    float yx = d * Sv.x;
    float yy = d * Sv.y;
    __half2 h2[8];
#pragma unroll
    for (int c = 0; c < 4; c++) {
        float4 w0 = ((const float4*)W1)[c];          // W1 row 0
        float4 w1 = ((const float4*)(W1 + 16))[c];   // W1 row 1
        float4 bb = ((const float4*)b1)[c];
        float hx = d * fmaxf(fmaf(yx, w0.x, fmaf(yy, w1.x, bb.x)), 0.0f);
        float hy = d * fmaxf(fmaf(yx, w0.y, fmaf(yy, w1.y, bb.y)), 0.0f);
        float hz = d * fmaxf(fmaf(yx, w0.z, fmaf(yy, w1.z, bb.z)), 0.0f);
        float hw = d * fmaxf(fmaf(yx, w0.w, fmaf(yy, w1.w, bb.w)), 0.0f);
        h2[2 * c + 0] = __floats2half2_rn(hx, hy);
        h2[2 * c + 1] = __floats2half2_rn(hz, hw);
    }
    uint4* pq = (uint4*)h2;
    st256(&g_q2h[i * 2], pq[0], pq[1]);
    st256(&g_S2h[i * 2], pq[0], pq[1]);   // self loop
}

// 2 edges per thread: 2 index loads, 2x256-bit gathers, then 4x128-bit reds.
__global__ void __launch_bounds__(512) k_edge2(const void* __restrict__ ei) {
    long long e = ((long long)blockIdx.x * blockDim.x + threadIdx.x) * 2;
    if (e >= NE) return;
    int s0, s1, t0, t1;
    if (g_is64) {
        longlong2 sv = __ldcg((const longlong2*)((const long long*)ei + e));
        longlong2 tv = __ldcg((const longlong2*)((const long long*)ei + NE + e));
        s0 = (int)sv.x; s1 = (int)sv.y; t0 = (int)tv.x; t1 = (int)tv.y;
    } else {
        int2 sv = __ldcg((const int2*)((const int*)ei + e));
        int2 tv = __ldcg((const int2*)((const int*)ei + NE + e));
        s0 = sv.x; s1 = sv.y; t0 = tv.x; t1 = tv.y;
    }
    unsigned a0, a1, a2, a3, a4, a5, a6, a7;
    unsigned b0, b1, b2, b3, b4, b5, b6, b7;
    asm volatile("ld.global.cg.v8.b32 {%0,%1,%2,%3,%4,%5,%6,%7}, [%8];"
                 : "=r"(a0), "=r"(a1), "=r"(a2), "=r"(a3),
                   "=r"(a4), "=r"(a5), "=r"(a6), "=r"(a7)
                 : "l"(&g_q2h[(long long)s0 * 2]));
    asm volatile("ld.global.cg.v8.b32 {%0,%1,%2,%3,%4,%5,%6,%7}, [%8];"
                 : "=r"(b0), "=r"(b1), "=r"(b2), "=r"(b3),
                   "=r"(b4), "=r"(b5), "=r"(b6), "=r"(b7)
                 : "l"(&g_q2h[(long long)s1 * 2]));
    uint4* d0 = &g_S2h[(long long)t0 * 2];
    uint4* d1 = &g_S2h[(long long)t1 * 2];
    asm volatile("red.global.add.noftz.v4.f16x2 [%0], {%1,%2,%3,%4};"
                 :: "l"(d0), "r"(a0), "r"(a1), "r"(a2), "r"(a3) : "memory");
    asm volatile("red.global.add.noftz.v4.f16x2 [%0], {%1,%2,%3,%4};"
                 :: "l"(d0 + 1), "r"(a4), "r"(a5), "r"(a6), "r"(a7) : "memory");
    asm volatile("red.global.add.noftz.v4.f16x2 [%0], {%1,%2,%3,%4};"
                 :: "l"(d1), "r"(b0), "r"(b1), "r"(b2), "r"(b3) : "memory");
    asm volatile("red.global.add.noftz.v4.f16x2 [%0], {%1,%2,%3,%4};"
                 :: "l"(d1 + 1), "r"(b4), "r"(b5), "r"(b6), "r"(b7) : "memory");
}

// Packed fp32x2 FMA (Blackwell sm_100a+): d = a*b + c on two f32 lanes.
__device__ __forceinline__ unsigned long long fma_f32x2(
    unsigned long long a, unsigned long long b, unsigned long long c) {
    unsigned long long d;
    asm("fma.rn.f32x2 %0, %1, %2, %3;" : "=l"(d) : "l"(a), "l"(b), "l"(c));
    return d;
}
__device__ __forceinline__ unsigned long long pack2(float lo, float hi) {
    unsigned long long r;
    asm("mov.b64 %0, {%1, %2};" : "=l"(r) : "f"(lo), "f"(hi));
    return r;
}
__device__ __forceinline__ float2 unpack2(unsigned long long v) {
    float lo, hi;
    asm("mov.b64 {%0, %1}, %2;" : "=f"(lo), "=f"(hi) : "l"(v));
    return make_float2(lo, hi);
}

__global__ void k_pool(const void* __restrict__ batch,
                       const float* __restrict__ W2, const float* __restrict__ b2,
                       const float* __restrict__ Wl) {
    // W2 as pairs along the 32-output axis: sW2p[j][kp] = (W2[j][2kp], W2[j][2kp+1])
    __shared__ unsigned long long sW2p[16 * 16];
    __shared__ unsigned long long sb2p[16];
    __shared__ unsigned long long sWlp[16];
    for (int j = threadIdx.x; j < 256; j += blockDim.x)
        sW2p[j] = ((const unsigned long long*)W2)[j];
    if (threadIdx.x < 16) {
        sb2p[threadIdx.x] = ((const unsigned long long*)b2)[threadIdx.x];
        sWlp[threadIdx.x] = ((const unsigned long long*)Wl)[threadIdx.x];
    }
    __syncthreads();

    int i = blockIdx.x * blockDim.x + threadIdx.x;
    float val = 0.0f;
    int g = -1;
    if (i < NN) {
        float d = g_dinv[i];
        uint4 a = __ldcg(&g_S2h[i * 2 + 0]);
        uint4 b = __ldcg(&g_S2h[i * 2 + 1]);
        unsigned long long zz[16];        // (z[j], z[j]) broadcast pairs
        const __half2* ah = (const __half2*)&a;
        const __half2* bh = (const __half2*)&b;
#pragma unroll
        for (int j = 0; j < 4; j++) {
            float2 f = __half22float2(ah[j]);
            zz[2 * j + 0] = pack2(d * f.x, d * f.x);
            zz[2 * j + 1] = pack2(d * f.y, d * f.y);
            float2 f2 = __half22float2(bh[j]);
            zz[8 + 2 * j + 0] = pack2(d * f2.x, d * f2.x);
            zz[8 + 2 * j + 1] = pack2(d * f2.y, d * f2.y);
        }
        float s = 0.0f;
#pragma unroll
        for (int kp = 0; kp < 16; kp++) {
            unsigned long long acc = sb2p[kp];
#pragma unroll
            for (int j = 0; j < 16; j++)
                acc = fma_f32x2(zz[j], sW2p[j * 16 + kp], acc);
            float2 u = unpack2(acc);
            float2 wl = unpack2(sWlp[kp]);
            s = fmaf(fmaxf(u.x, 0.0f), wl.x, s);
            s = fmaf(fmaxf(u.y, 0.0f), wl.y, s);
        }
        val = s;
        g = g_is64 ? (int)__ldcg((const long long*)batch + i)
                   : __ldcg((const int*)batch + i);
    }

    // batch is sorted -> contiguous equal-g runs. Segmented warp reduction to
    // avoid ~500k same-address global atomics.
    float cnt = (g >= 0) ? 1.0f : 0.0f;
    const unsigned full = 0xffffffffu;
    int lane = threadIdx.x & 31;
#pragma unroll
    for (int off = 1; off < 32; off <<= 1) {
        float vo = __shfl_down_sync(full, val, off);
        float co = __shfl_down_sync(full, cnt, off);
        int   go = __shfl_down_sync(full, g,   off);
        if (lane + off < 32 && go == g) { val += vo; cnt += co; }
    }
    int gup = __shfl_up_sync(full, g, 1);
    if (g >= 0 && (lane == 0 || gup != g)) {
        atomicAdd(&g_psum[g], val);
        atomicAdd(&g_pcnt[g], cnt);
    }
}

__global__ void k_out(float* __restrict__ out, const float* __restrict__ bl) {
    int g = blockIdx.x * blockDim.x + threadIdx.x;
    if (g < NG) out[g] = g_psum[g] / fmaxf(g_pcnt[g], 1.0f) + bl[0];
}

extern "C" void kernel_launch(void* const* d_in, const int* in_sizes, int n_in,
                              void* d_out, int out_size) {
    const float* x     = (const float*)d_in[0];
    const void*  ei    = d_in[1];
    const void*  batch = d_in[2];
    const float* W1    = (const float*)d_in[3];
    const float* b1    = (const float*)d_in[4];
    const float* W2    = (const float*)d_in[5];
    const float* b2    = (const float*)d_in[6];
    const float* Wl    = (const float*)d_in[7];
    const float* bl    = (const float*)d_in[8];
    float* out = (float*)d_out;

    const int TB = 256;
    const int EB = 512;                   // edge kernels: bigger blocks
    k_init  <<<(NN + TB - 1) / TB, TB>>>(ei);
    k_degree<<<(NE / 4 + EB - 1) / EB, EB>>>(ei);
    k_prep1 <<<(NN + TB - 1) / TB, TB>>>(x);
    k_edge1 <<<(NE / 4 + EB - 1) / EB, EB>>>(ei);
    k_mid   <<<(NN + TB - 1) / TB, TB>>>(W1, b1);
    k_edge2 <<<(NE / 2 + EB - 1) / EB, EB>>>(ei);
    k_pool  <<<(NN + TB - 1) / TB, TB>>>(batch, W2, b2, Wl);
    k_out   <<<(NG + TB - 1) / TB, TB>>>(out, bl);
}